// round 15
// baseline (speedup 1.0000x reference)
#include <cuda_runtime.h>
#include <cuda_fp16.h>
#include <cstdint>

#define NN   50000
#define EE   800000
#define DIN  128
#define DH   512
#define DOUT 256
#define GG   512
#define NBLK 196                      // ceil(NN/256)

// ---------------------------------------------------------------------------
__device__ __align__(16) float g_pool[GG * DH];
__device__ float g_cnt[GG];

// CSR scratch
__device__ int g_deg[NN];
__device__ int g_fill[NN];
__device__ int g_offs[NN];
__device__ int g_bsum[256];
__device__ int g_eidx[EE];

// Activation ping-pong, fp16
__device__ __align__(16) __half g_a0[NN * DH];
__device__ __align__(16) __half g_a1[NN * DH];

// Weights, transposed to [n][k], fp16
__device__ __align__(16) __half g_w1[DH * DIN];
__device__ __align__(16) __half g_w2[DH * DH];
__device__ __align__(16) __half g_w3[DH * DH];
__device__ __align__(16) __half g_w4[DH * DH];

// ---------------------------------------------------------------------------
__device__ __forceinline__ uint32_t smem_u32(const void* p) {
    uint32_t a;
    asm("{ .reg .u64 t; cvta.to.shared.u64 t, %1; cvt.u32.u64 %0, t; }"
        : "=r"(a) : "l"(p));
    return a;
}
#define CP16(dst, src) \
    asm volatile("cp.async.cg.shared.global [%0], [%1], 16;" :: "r"(dst), "l"(src))
#define CP_COMMIT() asm volatile("cp.async.commit_group;" ::: "memory")
#define CP_WAITN(n) asm volatile("cp.async.wait_group %0;" :: "n"(n) : "memory")
#define LDSM_X4(r0, r1, r2, r3, addr) \
    asm volatile("ldmatrix.sync.aligned.m8n8.x4.shared.b16 {%0,%1,%2,%3}, [%4];" \
                 : "=r"(r0), "=r"(r1), "=r"(r2), "=r"(r3) : "r"(addr))

__device__ __forceinline__ void red_v2(float* p, float a, float b) {
    asm volatile("red.global.add.v2.f32 [%0], {%1,%2};"
                 :: "l"(p), "f"(a), "f"(b) : "memory");
}

__device__ __forceinline__ void mma16816(float* d, const uint32_t* a,
                                         const uint32_t* b) {
    asm volatile(
        "mma.sync.aligned.m16n8k16.row.col.f32.f16.f16.f32 "
        "{%0,%1,%2,%3}, {%4,%5,%6,%7}, {%8,%9}, {%0,%1,%2,%3};"
        : "+f"(d[0]), "+f"(d[1]), "+f"(d[2]), "+f"(d[3])
        : "r"(a[0]), "r"(a[1]), "r"(a[2]), "r"(a[3]), "r"(b[0]), "r"(b[1]));
}

// ---------------------------------------------------------------------------
// prep0: convW x4 + zero deg/fill/pool + graph counts via binary search
#define T_W1   (512 * DIN)
#define T_W2   (T_W1 + 512 * DH)
#define T_W3   (T_W2 + 512 * DH)
#define T_W4   (T_W3 + 512 * DH)
#define T_ZN   (T_W4 + NN)
#define T_ZP   (T_ZN + GG * DH)
#define T_CNT  (T_ZP + GG)
#define PREP_THREADS T_CNT

__device__ __forceinline__ void convW_one(const float* __restrict__ W, int Kd,
                                          __half* __restrict__ o, int i) {
    int n = i / Kd;
    int k = i - n * Kd;
    o[i] = __float2half_rn(W[(size_t)k * 512 + n]);
}

__global__ void prep0_kernel(const float* __restrict__ W1,
                             const float* __restrict__ W2,
                             const float* __restrict__ W3,
                             const float* __restrict__ W4,
                             const int* __restrict__ batch) {
    int i = blockIdx.x * blockDim.x + threadIdx.x;
    if (i < T_W1) {
        convW_one(W1, DIN, g_w1, i);
    } else if (i < T_W2) {
        convW_one(W2, DH, g_w2, i - T_W1);
    } else if (i < T_W3) {
        convW_one(W3, DH, g_w3, i - T_W2);
    } else if (i < T_W4) {
        convW_one(W4, DH, g_w4, i - T_W3);
    } else if (i < T_ZN) {
        int j = i - T_W4;
        g_deg[j] = 0;
        g_fill[j] = 0;
    } else if (i < T_ZP) {
        g_pool[i - T_ZN] = 0.f;
    } else if (i < T_CNT) {
        int g = i - T_ZP;
        int lo = 0, hi = NN;
        while (lo < hi) { int m = (lo + hi) >> 1; if (__ldg(&batch[m]) < g) lo = m + 1; else hi = m; }
        int lb = lo;
        lo = 0; hi = NN;
        while (lo < hi) { int m = (lo + hi) >> 1; if (__ldg(&batch[m]) < g + 1) lo = m + 1; else hi = m; }
        g_cnt[g] = (float)(lo - lb);
    }
}

// ---------------------------------------------------------------------------
__global__ void hist_kernel(const int* __restrict__ ei) {
    int i = blockIdx.x * blockDim.x + threadIdx.x;
    if (i < EE) atomicAdd(&g_deg[__ldg(&ei[EE + i])], 1);
}

__global__ void scan1_kernel() {
    __shared__ int s[256];
    int tid = threadIdx.x;
    int idx = blockIdx.x * 256 + tid;
    int v = (idx < NN) ? g_deg[idx] : 0;
    s[tid] = v;
    __syncthreads();
#pragma unroll
    for (int d = 1; d < 256; d <<= 1) {
        int t = (tid >= d) ? s[tid - d] : 0;
        __syncthreads();
        s[tid] += t;
        __syncthreads();
    }
    if (idx < NN) g_offs[idx] = s[tid] - v;
    if (tid == 255) g_bsum[blockIdx.x] = s[255];
}

__global__ void scan2_kernel() {
    __shared__ int s[256];
    int tid = threadIdx.x;
    int v = (tid < NBLK) ? g_bsum[tid] : 0;
    s[tid] = v;
    __syncthreads();
#pragma unroll
    for (int d = 1; d < 256; d <<= 1) {
        int t = (tid >= d) ? s[tid - d] : 0;
        __syncthreads();
        s[tid] += t;
        __syncthreads();
    }
    g_bsum[tid] = s[tid] - v;
}

__global__ void scatter_kernel(const int* __restrict__ ei) {
    int e = blockIdx.x * blockDim.x + threadIdx.x;
    if (e >= EE) return;
    int src = __ldg(&ei[e]);
    int dst = __ldg(&ei[EE + e]);
    int pos = g_offs[dst] + g_bsum[dst >> 8] + atomicAdd(&g_fill[dst], 1);
    g_eidx[pos] = src;
}

// warp-per-node: acc = x[n] + sum_j x[eidx[j]]; emit fp16 directly
__global__ void csr_agg_kernel(const float* __restrict__ x) {
    int n = (blockIdx.x * blockDim.x + threadIdx.x) >> 5;
    if (n >= NN) return;
    int lane = threadIdx.x & 31;
    int base = g_offs[n] + g_bsum[n >> 8];
    int deg = g_deg[n];
    const float4* xr = (const float4*)x;

    float4 acc = __ldg(&xr[(size_t)n * 32 + lane]);
#pragma unroll 8
    for (int j = 0; j < deg; j++) {
        int s = __ldg(&g_eidx[base + j]);
        float4 v = __ldg(&xr[(size_t)s * 32 + lane]);
        acc.x += v.x; acc.y += v.y; acc.z += v.z; acc.w += v.w;
    }

    __half2 h01 = __floats2half2_rn(acc.x, acc.y);
    __half2 h23 = __floats2half2_rn(acc.z, acc.w);
    ((uint2*)(g_a0 + (size_t)n * DIN))[lane] =
        make_uint2(*(uint32_t*)&h01, *(uint32_t*)&h23);
}

// ---------------------------------------------------------------------------
// GEMM: A staged in SMEM (full K), CTA tile 128x256 over 2 n-iterations.
// 8 warps (2m x 4n), warp tile 64x64. W 3-stage cp.async, K-chunk 32.
#define LDA         40                         // W tile row stride (fp16)
#define WTILE_BYTES (256 * LDA * 2)            // 20480 per stage
#define NSTAGE      3
#define GT          256

// SMEM layout: [A buffer (128 x (Kd+8))] [W stages x3]
#define A_BYTES_MAX (128 * (DH + 8) * 2)       // 133120
#define GEMM_SMEM   (A_BYTES_MAX + NSTAGE * WTILE_BYTES)   // 194560

__device__ __forceinline__ void issue_w(uint32_t sw,
                                        const __half* __restrict__ B,
                                        int kb, int Kd, int tid) {
    // 256 rows x 4 segs = 1024 CP16; 4 per thread
#pragma unroll
    for (int j = 0; j < 4; j++) {
        int idx = tid + GT * j;
        int row = idx >> 2;
        int seg = idx & 3;
        CP16(sw + row * (LDA * 2) + seg * 16,
             B + (size_t)row * Kd + kb + seg * 8);
    }
}

// ACT: 0 -> fused mean-pool red.v2; 1 -> LeakyReLU(1.5); 2 -> ReLU.
template <int ACT>
__global__ __launch_bounds__(GT, 1)
void gemm_mma_kernel(const __half* __restrict__ A,
                     const __half* __restrict__ B,
                     const float* __restrict__ bias,
                     __half* __restrict__ O,
                     const int* __restrict__ batch,
                     int M, int Kd) {
    extern __shared__ char smem[];
    const uint32_t s0 = smem_u32(smem);
    const int ldA = Kd + 8;                    // fp16 elems per A row
    const uint32_t sW0 = s0 + (uint32_t)(128 * ldA * 2);

    const int tid  = threadIdx.x;
    const int warp = tid >> 5;
    const int lane = tid & 31;
    const int gid  = lane >> 2;
    const int tig  = lane & 3;
    const int wm = (warp >> 2) * 64;           // 0, 64
    const int wn = (warp & 3) * 64;            // 0, 64, 128, 192
    const int m0 = blockIdx.x * 128;

    // ---- stage A (128 x Kd) into SMEM via cp.async ----
    {
        const int nchunks16 = 128 * Kd / 8;    // CP16 count
        for (int idx = tid; idx < nchunks16; idx += GT) {
            int row = idx / (Kd / 8);
            int k8  = idx - row * (Kd / 8);
            int ar = m0 + row;
            if (ar >= M) ar = M - 1;
            CP16(s0 + (uint32_t)(row * ldA * 2) + k8 * 16,
                 A + (size_t)ar * Kd + k8 * 8);
        }
        CP_COMMIT();
    }

    // A fragment base offset (within A buffer), per warp/lane
    const uint32_t aOff =
        ((wm + (lane & 15)) * ldA + ((lane >> 4) << 3)) * 2;
    const uint32_t bOff =
        ((wn + (lane & 7) + (((lane >> 4) & 1) << 3)) * LDA + (((lane >> 3) & 1) << 3)) * 2;

    const int NCHUNK = Kd >> 5;

    for (int niter = 0; niter < 2; niter++) {
        const int n0 = niter * 256;
        const __half* Bn = B + (size_t)n0 * Kd;

        float acc[4][8][4] = {};

        // W prologue: 2 chunks in flight (groups also cover the A load on niter 0)
        issue_w(sW0 + 0 * WTILE_BYTES, Bn, 0, Kd, tid);
        CP_COMMIT();
        if (NCHUNK > 1) {
            issue_w(sW0 + 1 * WTILE_BYTES, Bn, 32, Kd, tid);
            CP_COMMIT();
        }

        int sbuf = 0;
        for (int c = 0; c < NCHUNK; c++) {
            if (c + 2 < NCHUNK) {
                int nb = sbuf + 2; if (nb >= NSTAGE) nb -= NSTAGE;
                issue_w(sW0 + nb * WTILE_BYTES, Bn, (c + 2) * 32, Kd, tid);
                CP_COMMIT();
                CP_WAITN(2);
            } else if (c + 1 < NCHUNK) {
                CP_WAITN(1);
            } else {
                CP_WAITN(0);
            }
            __syncthreads();

            const uint32_t sB = sW0 + sbuf * WTILE_BYTES;
            const int kb = c * 32;

#pragma unroll
            for (int k0 = 0; k0 < 32; k0 += 16) {
                uint32_t b[8][2];
#pragma unroll
                for (int np = 0; np < 4; np++) {
                    uint32_t off = bOff + (np * 16 * LDA + k0) * 2;
                    LDSM_X4(b[2 * np][0], b[2 * np][1],
                            b[2 * np + 1][0], b[2 * np + 1][1], sB + off);
                }
#pragma unroll
                for (int mt = 0; mt < 4; mt++) {
                    uint32_t off = aOff + (uint32_t)(mt * 16 * ldA + kb + k0) * 2;
                    uint32_t a[4];
                    LDSM_X4(a[0], a[1], a[2], a[3], s0 + off);
#pragma unroll
                    for (int nt = 0; nt < 8; nt++)
                        mma16816(acc[mt][nt], a, b[nt]);
                }
            }
            __syncthreads();
            if (++sbuf == NSTAGE) sbuf = 0;
        }

        // Epilogue for this n-iter
#pragma unroll
        for (int mt = 0; mt < 4; mt++) {
            int m1 = m0 + wm + mt * 16 + gid;
            int m2 = m1 + 8;
            int b1i = 0, b2i = 0;
            if (ACT == 0) {
                b1i = (m1 < M) ? __ldg(&batch[m1]) : 0;
                b2i = (m2 < M) ? __ldg(&batch[m2]) : 0;
            }
#pragma unroll
            for (int nt = 0; nt < 8; nt++) {
                int n = n0 + wn + nt * 8 + 2 * tig;
                float2 bb = *(const float2*)(bias + n);
                float f0 = acc[mt][nt][0] + bb.x;
                float f1 = acc[mt][nt][1] + bb.y;
                float f2 = acc[mt][nt][2] + bb.x;
                float f3 = acc[mt][nt][3] + bb.y;
                if (ACT == 1) {
                    f0 = f0 > 0.f ? f0 : 1.5f * f0;
                    f1 = f1 > 0.f ? f1 : 1.5f * f1;
                    f2 = f2 > 0.f ? f2 : 1.5f * f2;
                    f3 = f3 > 0.f ? f3 : 1.5f * f3;
                } else if (ACT == 2) {
                    f0 = fmaxf(f0, 0.f); f1 = fmaxf(f1, 0.f);
                    f2 = fmaxf(f2, 0.f); f3 = fmaxf(f3, 0.f);
                }
                if (ACT == 0) {
                    if (m1 < M) red_v2(&g_pool[b1i * DH + n], f0, f1);
                    if (m2 < M) red_v2(&g_pool[b2i * DH + n], f2, f3);
                } else {
                    if (m1 < M) {
                        __half2 hp = __floats2half2_rn(f0, f1);
                        *(__half2*)(O + (size_t)m1 * DH + n) = hp;
                    }
                    if (m2 < M) {
                        __half2 hp = __floats2half2_rn(f2, f3);
                        *(__half2*)(O + (size_t)m2 * DH + n) = hp;
                    }
                }
            }
        }
    }
}

// ---------------------------------------------------------------------------
__global__ void final_out_kernel(const float* __restrict__ Wl,
                                 const float* __restrict__ bl,
                                 float* __restrict__ out) {
    __shared__ float p[DH];
    __shared__ float red[DOUT];
    int g = blockIdx.x;
    int t = threadIdx.x;

    float inv_cnt = 1.0f / fmaxf(g_cnt[g], 1.0f);
    for (int k = t; k < DH; k += DOUT)
        p[k] = g_pool[g * DH + k] * inv_cnt;
    __syncthreads();

    float acc = bl[t];
#pragma unroll 8
    for (int k = 0; k < DH; k++)
        acc += p[k] * Wl[k * DOUT + t];

    red[t] = acc * acc;
    __syncthreads();
    for (int s = DOUT / 2; s > 0; s >>= 1) {
        if (t < s) red[t] += red[t + s];
        __syncthreads();
    }
    float nrm = fmaxf(sqrtf(red[0]), 1e-12f);
    out[g * DOUT + t] = acc / nrm;
}

// ---------------------------------------------------------------------------
extern "C" void kernel_launch(void* const* d_in, const int* in_sizes, int n_in,
                              void* d_out, int out_size) {
    const float* x     = (const float*)d_in[0];
    const int*   ei    = (const int*)d_in[1];
    const int*   batch = (const int*)d_in[2];
    const float* W1 = (const float*)d_in[3];
    const float* b1 = (const float*)d_in[4];
    const float* W2 = (const float*)d_in[5];
    const float* b2 = (const float*)d_in[6];
    const float* W3 = (const float*)d_in[7];
    const float* b3 = (const float*)d_in[8];
    const float* W4 = (const float*)d_in[9];
    const float* b4 = (const float*)d_in[10];
    const float* Wl = (const float*)d_in[11];
    const float* bl = (const float*)d_in[12];
    float* out = (float*)d_out;

    __half *a0, *a1, *w1, *w2, *w3, *w4;
    cudaGetSymbolAddress((void**)&a0, g_a0);
    cudaGetSymbolAddress((void**)&a1, g_a1);
    cudaGetSymbolAddress((void**)&w1, g_w1);
    cudaGetSymbolAddress((void**)&w2, g_w2);
    cudaGetSymbolAddress((void**)&w3, g_w3);
    cudaGetSymbolAddress((void**)&w4, g_w4);

    cudaFuncSetAttribute(gemm_mma_kernel<0>, cudaFuncAttributeMaxDynamicSharedMemorySize, GEMM_SMEM);
    cudaFuncSetAttribute(gemm_mma_kernel<1>, cudaFuncAttributeMaxDynamicSharedMemorySize, GEMM_SMEM);
    cudaFuncSetAttribute(gemm_mma_kernel<2>, cudaFuncAttributeMaxDynamicSharedMemorySize, GEMM_SMEM);

    // 1) prep (convW, zeros, counts) + CSR build + aggregation
    prep0_kernel<<<(PREP_THREADS + 255) / 256, 256>>>(W1, W2, W3, W4, batch);
    hist_kernel<<<(EE + 255) / 256, 256>>>(ei);
    scan1_kernel<<<NBLK, 256>>>();
    scan2_kernel<<<1, 256>>>();
    scatter_kernel<<<(EE + 255) / 256, 256>>>(ei);
    csr_agg_kernel<<<(NN * 32 + 255) / 256, 256>>>(x);

    // 2) 4-layer MLP (A staged in SMEM, 2 n-iters/CTA); layer 4 fuses pool
    int grid = (NN + 127) / 128;
    gemm_mma_kernel<1><<<grid, GT, GEMM_SMEM>>>(a0, w1, b1, a1, nullptr, NN, DIN);
    gemm_mma_kernel<2><<<grid, GT, GEMM_SMEM>>>(a1, w2, b2, a0, nullptr, NN, DH);
    gemm_mma_kernel<2><<<grid, GT, GEMM_SMEM>>>(a0, w3, b3, a1, nullptr, NN, DH);
    gemm_mma_kernel<0><<<grid, GT, GEMM_SMEM>>>(a1, w4, b4, nullptr, batch, NN, DH);

    // 3) final linear + L2 normalize
    final_out_kernel<<<GG, DOUT>>>(Wl, bl, out);
}

// round 16
// speedup vs baseline: 1.2227x; 1.2227x over previous
#include <cuda_runtime.h>
#include <cuda_fp16.h>
#include <cstdint>

#define NN   50000
#define EE   800000
#define DIN  128
#define DH   512
#define DOUT 256
#define GG   512
#define NBLK 196                      // ceil(NN/256)

// ---------------------------------------------------------------------------
__device__ __align__(16) float g_pool[GG * DH];
__device__ float g_cnt[GG];

// CSR scratch
__device__ int g_deg[NN];
__device__ int g_fill[NN];
__device__ int g_offs[NN];
__device__ int g_bsum[256];
__device__ int g_eidx[EE];

// Activation ping-pong, fp16
__device__ __align__(16) __half g_a0[NN * DH];
__device__ __align__(16) __half g_a1[NN * DH];

// Weights, transposed to [n][k], fp16
__device__ __align__(16) __half g_w1[DH * DIN];
__device__ __align__(16) __half g_w2[DH * DH];
__device__ __align__(16) __half g_w3[DH * DH];
__device__ __align__(16) __half g_w4[DH * DH];

// ---------------------------------------------------------------------------
__device__ __forceinline__ uint32_t smem_u32(const void* p) {
    uint32_t a;
    asm("{ .reg .u64 t; cvta.to.shared.u64 t, %1; cvt.u32.u64 %0, t; }"
        : "=r"(a) : "l"(p));
    return a;
}
#define CP16(dst, src) \
    asm volatile("cp.async.cg.shared.global [%0], [%1], 16;" :: "r"(dst), "l"(src))
#define CP_COMMIT() asm volatile("cp.async.commit_group;" ::: "memory")
#define CP_WAITN(n) asm volatile("cp.async.wait_group %0;" :: "n"(n) : "memory")
#define LDSM_X4(r0, r1, r2, r3, addr) \
    asm volatile("ldmatrix.sync.aligned.m8n8.x4.shared.b16 {%0,%1,%2,%3}, [%4];" \
                 : "=r"(r0), "=r"(r1), "=r"(r2), "=r"(r3) : "r"(addr))

__device__ __forceinline__ void red_v2(float* p, float a, float b) {
    asm volatile("red.global.add.v2.f32 [%0], {%1,%2};"
                 :: "l"(p), "f"(a), "f"(b) : "memory");
}

__device__ __forceinline__ void mma16816(float* d, const uint32_t* a,
                                         const uint32_t* b) {
    asm volatile(
        "mma.sync.aligned.m16n8k16.row.col.f32.f16.f16.f32 "
        "{%0,%1,%2,%3}, {%4,%5,%6,%7}, {%8,%9}, {%0,%1,%2,%3};"
        : "+f"(d[0]), "+f"(d[1]), "+f"(d[2]), "+f"(d[3])
        : "r"(a[0]), "r"(a[1]), "r"(a[2]), "r"(a[3]), "r"(b[0]), "r"(b[1]));
}

// ---------------------------------------------------------------------------
// prep0: convW x4 + zero deg/fill/pool + graph counts via binary search
#define T_W1   (512 * DIN)
#define T_W2   (T_W1 + 512 * DH)
#define T_W3   (T_W2 + 512 * DH)
#define T_W4   (T_W3 + 512 * DH)
#define T_ZN   (T_W4 + NN)
#define T_ZP   (T_ZN + GG * DH)
#define T_CNT  (T_ZP + GG)
#define PREP_THREADS T_CNT

__device__ __forceinline__ void convW_one(const float* __restrict__ W, int Kd,
                                          __half* __restrict__ o, int i) {
    int n = i / Kd;
    int k = i - n * Kd;
    o[i] = __float2half_rn(W[(size_t)k * 512 + n]);
}

__global__ void prep0_kernel(const float* __restrict__ W1,
                             const float* __restrict__ W2,
                             const float* __restrict__ W3,
                             const float* __restrict__ W4,
                             const int* __restrict__ batch) {
    int i = blockIdx.x * blockDim.x + threadIdx.x;
    if (i < T_W1) {
        convW_one(W1, DIN, g_w1, i);
    } else if (i < T_W2) {
        convW_one(W2, DH, g_w2, i - T_W1);
    } else if (i < T_W3) {
        convW_one(W3, DH, g_w3, i - T_W2);
    } else if (i < T_W4) {
        convW_one(W4, DH, g_w4, i - T_W3);
    } else if (i < T_ZN) {
        int j = i - T_W4;
        g_deg[j] = 0;
        g_fill[j] = 0;
    } else if (i < T_ZP) {
        g_pool[i - T_ZN] = 0.f;
    } else if (i < T_CNT) {
        int g = i - T_ZP;
        int lo = 0, hi = NN;
        while (lo < hi) { int m = (lo + hi) >> 1; if (__ldg(&batch[m]) < g) lo = m + 1; else hi = m; }
        int lb = lo;
        lo = 0; hi = NN;
        while (lo < hi) { int m = (lo + hi) >> 1; if (__ldg(&batch[m]) < g + 1) lo = m + 1; else hi = m; }
        g_cnt[g] = (float)(lo - lb);
    }
}

// ---------------------------------------------------------------------------
__global__ void hist_kernel(const int* __restrict__ ei) {
    int i = blockIdx.x * blockDim.x + threadIdx.x;
    if (i < EE) atomicAdd(&g_deg[__ldg(&ei[EE + i])], 1);
}

__global__ void scan1_kernel() {
    __shared__ int s[256];
    int tid = threadIdx.x;
    int idx = blockIdx.x * 256 + tid;
    int v = (idx < NN) ? g_deg[idx] : 0;
    s[tid] = v;
    __syncthreads();
#pragma unroll
    for (int d = 1; d < 256; d <<= 1) {
        int t = (tid >= d) ? s[tid - d] : 0;
        __syncthreads();
        s[tid] += t;
        __syncthreads();
    }
    if (idx < NN) g_offs[idx] = s[tid] - v;
    if (tid == 255) g_bsum[blockIdx.x] = s[255];
}

__global__ void scan2_kernel() {
    __shared__ int s[256];
    int tid = threadIdx.x;
    int v = (tid < NBLK) ? g_bsum[tid] : 0;
    s[tid] = v;
    __syncthreads();
#pragma unroll
    for (int d = 1; d < 256; d <<= 1) {
        int t = (tid >= d) ? s[tid - d] : 0;
        __syncthreads();
        s[tid] += t;
        __syncthreads();
    }
    g_bsum[tid] = s[tid] - v;
}

__global__ void scatter_kernel(const int* __restrict__ ei) {
    int e = blockIdx.x * blockDim.x + threadIdx.x;
    if (e >= EE) return;
    int src = __ldg(&ei[e]);
    int dst = __ldg(&ei[EE + e]);
    int pos = g_offs[dst] + g_bsum[dst >> 8] + atomicAdd(&g_fill[dst], 1);
    g_eidx[pos] = src;
}

// warp-per-node: acc = x[n] + sum_j x[eidx[j]]; emit fp16 directly
__global__ void csr_agg_kernel(const float* __restrict__ x) {
    int n = (blockIdx.x * blockDim.x + threadIdx.x) >> 5;
    if (n >= NN) return;
    int lane = threadIdx.x & 31;
    int base = g_offs[n] + g_bsum[n >> 8];
    int deg = g_deg[n];
    const float4* xr = (const float4*)x;

    float4 acc = __ldg(&xr[(size_t)n * 32 + lane]);
#pragma unroll 8
    for (int j = 0; j < deg; j++) {
        int s = __ldg(&g_eidx[base + j]);
        float4 v = __ldg(&xr[(size_t)s * 32 + lane]);
        acc.x += v.x; acc.y += v.y; acc.z += v.z; acc.w += v.w;
    }

    __half2 h01 = __floats2half2_rn(acc.x, acc.y);
    __half2 h23 = __floats2half2_rn(acc.z, acc.w);
    ((uint2*)(g_a0 + (size_t)n * DIN))[lane] =
        make_uint2(*(uint32_t*)&h01, *(uint32_t*)&h23);
}

// ---------------------------------------------------------------------------
// GEMM (R14 structure): CTA 128x128, 4 warps (2m x 2n), warp tile 64x64,
// 3-stage cp.async, ONE barrier per K-chunk.
#define LDA         40
#define TILE_BYTES  (128 * LDA * 2)            // 10240
#define BUF_BYTES   (2 * TILE_BYTES)           // 20480 (A, B)
#define NSTAGE      3
#define GEMM_SMEM   (NSTAGE * BUF_BYTES)       // 61440
#define GT          128

__device__ __forceinline__ void issue_chunk(uint32_t sb,
                                            const __half* __restrict__ A,
                                            const __half* __restrict__ B,
                                            int m0, int n0, int M, int Kd, int kb,
                                            int tid) {
#pragma unroll
    for (int j = 0; j < 4; j++) {
        int idx = tid + GT * j;        // 0..511
        int row = idx >> 2;
        int seg = idx & 3;
        uint32_t doff = row * (LDA * 2) + seg * 16;
        int ar = m0 + row;
        if (ar >= M) ar = M - 1;
        CP16(sb + doff, A + (size_t)ar * Kd + kb + seg * 8);
    }
#pragma unroll
    for (int j = 0; j < 4; j++) {
        int idx = tid + GT * j;
        int row = idx >> 2;
        int seg = idx & 3;
        uint32_t doff = row * (LDA * 2) + seg * 16;
        CP16(sb + TILE_BYTES + doff, B + (size_t)(n0 + row) * Kd + kb + seg * 8);
    }
}

// ACT: 0 -> fused mean-pool red.v2; 1 -> LeakyReLU(1.5); 2 -> ReLU.
template <int ACT>
__global__ __launch_bounds__(GT, 2)
void gemm_mma_kernel(const __half* __restrict__ A,
                     const __half* __restrict__ B,
                     const float* __restrict__ bias,
                     __half* __restrict__ O,
                     const int* __restrict__ batch,
                     int M, int Kd) {
    extern __shared__ char smem[];
    const uint32_t s0 = smem_u32(smem);

    const int tid  = threadIdx.x;
    const int warp = tid >> 5;
    const int lane = tid & 31;
    const int gid  = lane >> 2;
    const int tig  = lane & 3;
    const int wm = (warp >> 1) * 64;   // 0, 64
    const int wn = (warp & 1) * 64;    // 0, 64
    const int m0 = blockIdx.y * 128;
    const int n0 = blockIdx.x * 128;

    const uint32_t aOff =
        ((wm + (lane & 15)) * LDA + ((lane >> 4) << 3)) * 2;
    const uint32_t bOff =
        ((wn + (lane & 7) + (((lane >> 4) & 1) << 3)) * LDA + (((lane >> 3) & 1) << 3)) * 2;

    float acc[4][8][4] = {};

    const int NCHUNK = Kd >> 5;

    // prologue: 2 chunks in flight
    issue_chunk(s0 + 0 * BUF_BYTES, A, B, m0, n0, M, Kd, 0, tid);
    CP_COMMIT();
    if (NCHUNK > 1) {
        issue_chunk(s0 + 1 * BUF_BYTES, A, B, m0, n0, M, Kd, 32, tid);
        CP_COMMIT();
    }

    int sbuf = 0;
    for (int c = 0; c < NCHUNK; c++) {
        // single barrier per iteration: publishes chunk c AND proves all warps
        // finished reading chunk c-1's buffer (so issuing into it is safe).
        if (c + 1 < NCHUNK) { CP_WAITN(1); } else { CP_WAITN(0); }
        __syncthreads();
        if (c + 2 < NCHUNK) {
            int nb = sbuf + 2; if (nb >= NSTAGE) nb -= NSTAGE;
            issue_chunk(s0 + nb * BUF_BYTES, A, B, m0, n0, M, Kd, (c + 2) * 32, tid);
            CP_COMMIT();
        }

        const uint32_t sb = s0 + sbuf * BUF_BYTES;
        const uint32_t sA = sb;
        const uint32_t sB = sb + TILE_BYTES;

#pragma unroll
        for (int k0 = 0; k0 < 32; k0 += 16) {
            uint32_t b[8][2];
#pragma unroll
            for (int np = 0; np < 4; np++) {
                uint32_t off = bOff + (np * 16 * LDA + k0) * 2;
                LDSM_X4(b[2 * np][0], b[2 * np][1],
                        b[2 * np + 1][0], b[2 * np + 1][1], sB + off);
            }
#pragma unroll
            for (int mt = 0; mt < 4; mt++) {
                uint32_t off = aOff + (mt * 16 * LDA + k0) * 2;
                uint32_t a[4];
                LDSM_X4(a[0], a[1], a[2], a[3], sA + off);
#pragma unroll
                for (int nt = 0; nt < 8; nt++)
                    mma16816(acc[mt][nt], a, b[nt]);
            }
        }
        if (++sbuf == NSTAGE) sbuf = 0;
    }

    // Epilogue
#pragma unroll
    for (int mt = 0; mt < 4; mt++) {
        int m1 = m0 + wm + mt * 16 + gid;
        int m2 = m1 + 8;
        int b1i = 0, b2i = 0;
        if (ACT == 0) {
            b1i = (m1 < M) ? __ldg(&batch[m1]) : 0;
            b2i = (m2 < M) ? __ldg(&batch[m2]) : 0;
        }
#pragma unroll
        for (int nt = 0; nt < 8; nt++) {
            int n = n0 + wn + nt * 8 + 2 * tig;
            float2 bb = *(const float2*)(bias + n);
            float f0 = acc[mt][nt][0] + bb.x;
            float f1 = acc[mt][nt][1] + bb.y;
            float f2 = acc[mt][nt][2] + bb.x;
            float f3 = acc[mt][nt][3] + bb.y;
            if (ACT == 1) {
                f0 = f0 > 0.f ? f0 : 1.5f * f0;
                f1 = f1 > 0.f ? f1 : 1.5f * f1;
                f2 = f2 > 0.f ? f2 : 1.5f * f2;
                f3 = f3 > 0.f ? f3 : 1.5f * f3;
            } else if (ACT == 2) {
                f0 = fmaxf(f0, 0.f); f1 = fmaxf(f1, 0.f);
                f2 = fmaxf(f2, 0.f); f3 = fmaxf(f3, 0.f);
            }
            if (ACT == 0) {
                if (m1 < M) red_v2(&g_pool[b1i * DH + n], f0, f1);
                if (m2 < M) red_v2(&g_pool[b2i * DH + n], f2, f3);
            } else {
                if (m1 < M) {
                    __half2 hp = __floats2half2_rn(f0, f1);
                    *(__half2*)(O + (size_t)m1 * DH + n) = hp;
                }
                if (m2 < M) {
                    __half2 hp = __floats2half2_rn(f2, f3);
                    *(__half2*)(O + (size_t)m2 * DH + n) = hp;
                }
            }
        }
    }
}

// ---------------------------------------------------------------------------
__global__ void final_out_kernel(const float* __restrict__ Wl,
                                 const float* __restrict__ bl,
                                 float* __restrict__ out) {
    __shared__ float p[DH];
    __shared__ float red[DOUT];
    int g = blockIdx.x;
    int t = threadIdx.x;

    float inv_cnt = 1.0f / fmaxf(g_cnt[g], 1.0f);
    for (int k = t; k < DH; k += DOUT)
        p[k] = g_pool[g * DH + k] * inv_cnt;
    __syncthreads();

    float acc = bl[t];
#pragma unroll 8
    for (int k = 0; k < DH; k++)
        acc += p[k] * Wl[k * DOUT + t];

    red[t] = acc * acc;
    __syncthreads();
    for (int s = DOUT / 2; s > 0; s >>= 1) {
        if (t < s) red[t] += red[t + s];
        __syncthreads();
    }
    float nrm = fmaxf(sqrtf(red[0]), 1e-12f);
    out[g * DOUT + t] = acc / nrm;
}

// ---------------------------------------------------------------------------
extern "C" void kernel_launch(void* const* d_in, const int* in_sizes, int n_in,
                              void* d_out, int out_size) {
    const float* x     = (const float*)d_in[0];
    const int*   ei    = (const int*)d_in[1];
    const int*   batch = (const int*)d_in[2];
    const float* W1 = (const float*)d_in[3];
    const float* b1 = (const float*)d_in[4];
    const float* W2 = (const float*)d_in[5];
    const float* b2 = (const float*)d_in[6];
    const float* W3 = (const float*)d_in[7];
    const float* b3 = (const float*)d_in[8];
    const float* W4 = (const float*)d_in[9];
    const float* b4 = (const float*)d_in[10];
    const float* Wl = (const float*)d_in[11];
    const float* bl = (const float*)d_in[12];
    float* out = (float*)d_out;

    __half *a0, *a1, *w1, *w2, *w3, *w4;
    cudaGetSymbolAddress((void**)&a0, g_a0);
    cudaGetSymbolAddress((void**)&a1, g_a1);
    cudaGetSymbolAddress((void**)&w1, g_w1);
    cudaGetSymbolAddress((void**)&w2, g_w2);
    cudaGetSymbolAddress((void**)&w3, g_w3);
    cudaGetSymbolAddress((void**)&w4, g_w4);

    cudaFuncSetAttribute(gemm_mma_kernel<0>, cudaFuncAttributeMaxDynamicSharedMemorySize, GEMM_SMEM);
    cudaFuncSetAttribute(gemm_mma_kernel<1>, cudaFuncAttributeMaxDynamicSharedMemorySize, GEMM_SMEM);
    cudaFuncSetAttribute(gemm_mma_kernel<2>, cudaFuncAttributeMaxDynamicSharedMemorySize, GEMM_SMEM);

    // 1) prep (convW, zeros, counts) + CSR build + aggregation
    prep0_kernel<<<(PREP_THREADS + 255) / 256, 256>>>(W1, W2, W3, W4, batch);
    hist_kernel<<<(EE + 255) / 256, 256>>>(ei);
    scan1_kernel<<<NBLK, 256>>>();
    scan2_kernel<<<1, 256>>>();
    scatter_kernel<<<(EE + 255) / 256, 256>>>(ei);
    csr_agg_kernel<<<(NN * 32 + 255) / 256, 256>>>(x);

    // 2) 4-layer MLP (single-pass fp16, 64x64 warp tiles, 1-barrier loop)
    dim3 grid(DH / 128, (NN + 127) / 128);
    gemm_mma_kernel<1><<<grid, GT, GEMM_SMEM>>>(a0, w1, b1, a1, nullptr, NN, DIN);
    gemm_mma_kernel<2><<<grid, GT, GEMM_SMEM>>>(a1, w2, b2, a0, nullptr, NN, DH);
    gemm_mma_kernel<2><<<grid, GT, GEMM_SMEM>>>(a0, w3, b3, a1, nullptr, NN, DH);
    gemm_mma_kernel<0><<<grid, GT, GEMM_SMEM>>>(a1, w4, b4, nullptr, batch, NN, DH);

    // 3) final linear + L2 normalize
    final_out_kernel<<<GG, DOUT>>>(Wl, bl, out);
}

// round 17
// speedup vs baseline: 1.4760x; 1.2072x over previous
#include <cuda_runtime.h>
#include <cuda_fp16.h>
#include <cstdint>

#define NN   50000
#define EE   800000
#define DIN  128
#define DH   512
#define DOUT 256
#define GG   512
#define NBLK 196                      // ceil(NN/256)

// ---------------------------------------------------------------------------
__device__ __align__(16) float g_pool[GG * DH];   // pooled h3 (fp32 sums)
__device__ __align__(16) float g_out2[GG * DH];   // pooled @ W4 + b4 (fp32)
__device__ float g_cnt[GG];

// CSR scratch
__device__ int g_deg[NN];
__device__ int g_fill[NN];
__device__ int g_offs[NN];
__device__ int g_bsum[256];
__device__ int g_eidx[EE];

// Activation ping-pong, fp16
__device__ __align__(16) __half g_a0[NN * DH];
__device__ __align__(16) __half g_a1[NN * DH];

// Weights, transposed to [n][k], fp16
__device__ __align__(16) __half g_w1[DH * DIN];
__device__ __align__(16) __half g_w2[DH * DH];
__device__ __align__(16) __half g_w3[DH * DH];
__device__ __align__(16) __half g_w4[DH * DH];

// ---------------------------------------------------------------------------
__device__ __forceinline__ uint32_t smem_u32(const void* p) {
    uint32_t a;
    asm("{ .reg .u64 t; cvta.to.shared.u64 t, %1; cvt.u32.u64 %0, t; }"
        : "=r"(a) : "l"(p));
    return a;
}
#define CP16(dst, src) \
    asm volatile("cp.async.cg.shared.global [%0], [%1], 16;" :: "r"(dst), "l"(src))
#define CP_COMMIT() asm volatile("cp.async.commit_group;" ::: "memory")
#define CP_WAITN(n) asm volatile("cp.async.wait_group %0;" :: "n"(n) : "memory")
#define LDSM_X4(r0, r1, r2, r3, addr) \
    asm volatile("ldmatrix.sync.aligned.m8n8.x4.shared.b16 {%0,%1,%2,%3}, [%4];" \
                 : "=r"(r0), "=r"(r1), "=r"(r2), "=r"(r3) : "r"(addr))

__device__ __forceinline__ void red_v2(float* p, float a, float b) {
    asm volatile("red.global.add.v2.f32 [%0], {%1,%2};"
                 :: "l"(p), "f"(a), "f"(b) : "memory");
}

__device__ __forceinline__ void mma16816(float* d, const uint32_t* a,
                                         const uint32_t* b) {
    asm volatile(
        "mma.sync.aligned.m16n8k16.row.col.f32.f16.f16.f32 "
        "{%0,%1,%2,%3}, {%4,%5,%6,%7}, {%8,%9}, {%0,%1,%2,%3};"
        : "+f"(d[0]), "+f"(d[1]), "+f"(d[2]), "+f"(d[3])
        : "r"(a[0]), "r"(a[1]), "r"(a[2]), "r"(a[3]), "r"(b[0]), "r"(b[1]));
}

// ---------------------------------------------------------------------------
// prep0: convW x4 + zero deg/fill/pool + graph counts via binary search
#define T_W1   (512 * DIN)
#define T_W2   (T_W1 + 512 * DH)
#define T_W3   (T_W2 + 512 * DH)
#define T_W4   (T_W3 + 512 * DH)
#define T_ZN   (T_W4 + NN)
#define T_ZP   (T_ZN + GG * DH)
#define T_CNT  (T_ZP + GG)
#define PREP_THREADS T_CNT

__device__ __forceinline__ void convW_one(const float* __restrict__ W, int Kd,
                                          __half* __restrict__ o, int i) {
    int n = i / Kd;
    int k = i - n * Kd;
    o[i] = __float2half_rn(W[(size_t)k * 512 + n]);
}

__global__ void prep0_kernel(const float* __restrict__ W1,
                             const float* __restrict__ W2,
                             const float* __restrict__ W3,
                             const float* __restrict__ W4,
                             const int* __restrict__ batch) {
    int i = blockIdx.x * blockDim.x + threadIdx.x;
    if (i < T_W1) {
        convW_one(W1, DIN, g_w1, i);
    } else if (i < T_W2) {
        convW_one(W2, DH, g_w2, i - T_W1);
    } else if (i < T_W3) {
        convW_one(W3, DH, g_w3, i - T_W2);
    } else if (i < T_W4) {
        convW_one(W4, DH, g_w4, i - T_W3);
    } else if (i < T_ZN) {
        int j = i - T_W4;
        g_deg[j] = 0;
        g_fill[j] = 0;
    } else if (i < T_ZP) {
        g_pool[i - T_ZN] = 0.f;
    } else if (i < T_CNT) {
        int g = i - T_ZP;
        int lo = 0, hi = NN;
        while (lo < hi) { int m = (lo + hi) >> 1; if (__ldg(&batch[m]) < g) lo = m + 1; else hi = m; }
        int lb = lo;
        lo = 0; hi = NN;
        while (lo < hi) { int m = (lo + hi) >> 1; if (__ldg(&batch[m]) < g + 1) lo = m + 1; else hi = m; }
        g_cnt[g] = (float)(lo - lb);
    }
}

// ---------------------------------------------------------------------------
__global__ void hist_kernel(const int* __restrict__ ei) {
    int i = blockIdx.x * blockDim.x + threadIdx.x;
    if (i < EE) atomicAdd(&g_deg[__ldg(&ei[EE + i])], 1);
}

__global__ void scan1_kernel() {
    __shared__ int s[256];
    int tid = threadIdx.x;
    int idx = blockIdx.x * 256 + tid;
    int v = (idx < NN) ? g_deg[idx] : 0;
    s[tid] = v;
    __syncthreads();
#pragma unroll
    for (int d = 1; d < 256; d <<= 1) {
        int t = (tid >= d) ? s[tid - d] : 0;
        __syncthreads();
        s[tid] += t;
        __syncthreads();
    }
    if (idx < NN) g_offs[idx] = s[tid] - v;
    if (tid == 255) g_bsum[blockIdx.x] = s[255];
}

__global__ void scan2_kernel() {
    __shared__ int s[256];
    int tid = threadIdx.x;
    int v = (tid < NBLK) ? g_bsum[tid] : 0;
    s[tid] = v;
    __syncthreads();
#pragma unroll
    for (int d = 1; d < 256; d <<= 1) {
        int t = (tid >= d) ? s[tid - d] : 0;
        __syncthreads();
        s[tid] += t;
        __syncthreads();
    }
    g_bsum[tid] = s[tid] - v;
}

__global__ void scatter_kernel(const int* __restrict__ ei) {
    int e = blockIdx.x * blockDim.x + threadIdx.x;
    if (e >= EE) return;
    int src = __ldg(&ei[e]);
    int dst = __ldg(&ei[EE + e]);
    int pos = g_offs[dst] + g_bsum[dst >> 8] + atomicAdd(&g_fill[dst], 1);
    g_eidx[pos] = src;
}

// warp-per-node: acc = x[n] + sum_j x[eidx[j]]; emit fp16 directly
__global__ void csr_agg_kernel(const float* __restrict__ x) {
    int n = (blockIdx.x * blockDim.x + threadIdx.x) >> 5;
    if (n >= NN) return;
    int lane = threadIdx.x & 31;
    int base = g_offs[n] + g_bsum[n >> 8];
    int deg = g_deg[n];
    const float4* xr = (const float4*)x;

    float4 acc = __ldg(&xr[(size_t)n * 32 + lane]);
#pragma unroll 8
    for (int j = 0; j < deg; j++) {
        int s = __ldg(&g_eidx[base + j]);
        float4 v = __ldg(&xr[(size_t)s * 32 + lane]);
        acc.x += v.x; acc.y += v.y; acc.z += v.z; acc.w += v.w;
    }

    __half2 h01 = __floats2half2_rn(acc.x, acc.y);
    __half2 h23 = __floats2half2_rn(acc.z, acc.w);
    ((uint2*)(g_a0 + (size_t)n * DIN))[lane] =
        make_uint2(*(uint32_t*)&h01, *(uint32_t*)&h23);
}

// ---------------------------------------------------------------------------
// GEMM: CTA 128x128, 4 warps (2m x 2n), warp tile 64x64, 3-stage cp.async,
// one barrier per K-chunk.
// ACT: 1 = LeakyReLU(1.5) store fp16; 2 = ReLU store fp16;
//      3 = ReLU + fused mean-pool red.v2 (no store);
//      4 = linear + bias, store fp32 (pooled GEMM).
#define LDA         40
#define TILE_BYTES  (128 * LDA * 2)            // 10240
#define BUF_BYTES   (2 * TILE_BYTES)           // 20480 (A, B)
#define NSTAGE      3
#define GEMM_SMEM   (NSTAGE * BUF_BYTES)       // 61440
#define GT          128

__device__ __forceinline__ void issue_chunk(uint32_t sb,
                                            const __half* __restrict__ A,
                                            const __half* __restrict__ B,
                                            int m0, int n0, int M, int Kd, int kb,
                                            int tid) {
#pragma unroll
    for (int j = 0; j < 4; j++) {
        int idx = tid + GT * j;        // 0..511
        int row = idx >> 2;
        int seg = idx & 3;
        uint32_t doff = row * (LDA * 2) + seg * 16;
        int ar = m0 + row;
        if (ar >= M) ar = M - 1;
        CP16(sb + doff, A + (size_t)ar * Kd + kb + seg * 8);
    }
#pragma unroll
    for (int j = 0; j < 4; j++) {
        int idx = tid + GT * j;
        int row = idx >> 2;
        int seg = idx & 3;
        uint32_t doff = row * (LDA * 2) + seg * 16;
        CP16(sb + TILE_BYTES + doff, B + (size_t)(n0 + row) * Kd + kb + seg * 8);
    }
}

template <int ACT>
__global__ __launch_bounds__(GT, 2)
void gemm_mma_kernel(const __half* __restrict__ A,
                     const __half* __restrict__ B,
                     const float* __restrict__ bias,
                     __half* __restrict__ O,
                     float* __restrict__ Of,
                     const int* __restrict__ batch,
                     int M, int Kd) {
    extern __shared__ char smem[];
    const uint32_t s0 = smem_u32(smem);

    const int tid  = threadIdx.x;
    const int warp = tid >> 5;
    const int lane = tid & 31;
    const int gid  = lane >> 2;
    const int tig  = lane & 3;
    const int wm = (warp >> 1) * 64;   // 0, 64
    const int wn = (warp & 1) * 64;    // 0, 64
    const int m0 = blockIdx.y * 128;
    const int n0 = blockIdx.x * 128;

    const uint32_t aOff =
        ((wm + (lane & 15)) * LDA + ((lane >> 4) << 3)) * 2;
    const uint32_t bOff =
        ((wn + (lane & 7) + (((lane >> 4) & 1) << 3)) * LDA + (((lane >> 3) & 1) << 3)) * 2;

    float acc[4][8][4] = {};

    const int NCHUNK = Kd >> 5;

    issue_chunk(s0 + 0 * BUF_BYTES, A, B, m0, n0, M, Kd, 0, tid);
    CP_COMMIT();
    if (NCHUNK > 1) {
        issue_chunk(s0 + 1 * BUF_BYTES, A, B, m0, n0, M, Kd, 32, tid);
        CP_COMMIT();
    }

    int sbuf = 0;
    for (int c = 0; c < NCHUNK; c++) {
        if (c + 1 < NCHUNK) { CP_WAITN(1); } else { CP_WAITN(0); }
        __syncthreads();
        if (c + 2 < NCHUNK) {
            int nb = sbuf + 2; if (nb >= NSTAGE) nb -= NSTAGE;
            issue_chunk(s0 + nb * BUF_BYTES, A, B, m0, n0, M, Kd, (c + 2) * 32, tid);
            CP_COMMIT();
        }

        const uint32_t sb = s0 + sbuf * BUF_BYTES;
        const uint32_t sA = sb;
        const uint32_t sB = sb + TILE_BYTES;

#pragma unroll
        for (int k0 = 0; k0 < 32; k0 += 16) {
            uint32_t b[8][2];
#pragma unroll
            for (int np = 0; np < 4; np++) {
                uint32_t off = bOff + (np * 16 * LDA + k0) * 2;
                LDSM_X4(b[2 * np][0], b[2 * np][1],
                        b[2 * np + 1][0], b[2 * np + 1][1], sB + off);
            }
#pragma unroll
            for (int mt = 0; mt < 4; mt++) {
                uint32_t off = aOff + (mt * 16 * LDA + k0) * 2;
                uint32_t a[4];
                LDSM_X4(a[0], a[1], a[2], a[3], sA + off);
#pragma unroll
                for (int nt = 0; nt < 8; nt++)
                    mma16816(acc[mt][nt], a, b[nt]);
            }
        }
        if (++sbuf == NSTAGE) sbuf = 0;
    }

    // Epilogue
#pragma unroll
    for (int mt = 0; mt < 4; mt++) {
        int m1 = m0 + wm + mt * 16 + gid;
        int m2 = m1 + 8;
        int b1i = 0, b2i = 0;
        if (ACT == 3) {
            b1i = (m1 < M) ? __ldg(&batch[m1]) : 0;
            b2i = (m2 < M) ? __ldg(&batch[m2]) : 0;
        }
#pragma unroll
        for (int nt = 0; nt < 8; nt++) {
            int n = n0 + wn + nt * 8 + 2 * tig;
            float2 bb = *(const float2*)(bias + n);
            float f0 = acc[mt][nt][0] + bb.x;
            float f1 = acc[mt][nt][1] + bb.y;
            float f2 = acc[mt][nt][2] + bb.x;
            float f3 = acc[mt][nt][3] + bb.y;
            if (ACT == 1) {
                f0 = f0 > 0.f ? f0 : 1.5f * f0;
                f1 = f1 > 0.f ? f1 : 1.5f * f1;
                f2 = f2 > 0.f ? f2 : 1.5f * f2;
                f3 = f3 > 0.f ? f3 : 1.5f * f3;
            } else if (ACT == 2 || ACT == 3) {
                f0 = fmaxf(f0, 0.f); f1 = fmaxf(f1, 0.f);
                f2 = fmaxf(f2, 0.f); f3 = fmaxf(f3, 0.f);
            }
            if (ACT == 3) {
                if (m1 < M) red_v2(&g_pool[b1i * DH + n], f0, f1);
                if (m2 < M) red_v2(&g_pool[b2i * DH + n], f2, f3);
            } else if (ACT == 4) {
                if (m1 < M) *(float2*)(Of + (size_t)m1 * DH + n) = make_float2(f0, f1);
                if (m2 < M) *(float2*)(Of + (size_t)m2 * DH + n) = make_float2(f2, f3);
            } else {
                if (m1 < M) {
                    __half2 hp = __floats2half2_rn(f0, f1);
                    *(__half2*)(O + (size_t)m1 * DH + n) = hp;
                }
                if (m2 < M) {
                    __half2 hp = __floats2half2_rn(f2, f3);
                    *(__half2*)(O + (size_t)m2 * DH + n) = hp;
                }
            }
        }
    }
}

// ---------------------------------------------------------------------------
// pooled sums -> mean -> fp16 (input for the 512x512 W4 GEMM)
__global__ void pool2half_kernel(__half* __restrict__ o) {
    int i = blockIdx.x * blockDim.x + threadIdx.x;
    if (i >= GG * DH) return;
    int g = i >> 9;
    float v = g_pool[i] / fmaxf(g_cnt[g], 1.0f);
    o[i] = __float2half_rn(v);
}

// out[g] = normalize( g_out2[g] @ Wl + bl )
__global__ void final_out_kernel(const float* __restrict__ Wl,
                                 const float* __restrict__ bl,
                                 float* __restrict__ out) {
    __shared__ float p[DH];
    __shared__ float red[DOUT];
    int g = blockIdx.x;
    int t = threadIdx.x;

    for (int k = t; k < DH; k += DOUT)
        p[k] = g_out2[g * DH + k];
    __syncthreads();

    float acc = bl[t];
#pragma unroll 8
    for (int k = 0; k < DH; k++)
        acc += p[k] * Wl[k * DOUT + t];

    red[t] = acc * acc;
    __syncthreads();
    for (int s = DOUT / 2; s > 0; s >>= 1) {
        if (t < s) red[t] += red[t + s];
        __syncthreads();
    }
    float nrm = fmaxf(sqrtf(red[0]), 1e-12f);
    out[g * DOUT + t] = acc / nrm;
}

// ---------------------------------------------------------------------------
extern "C" void kernel_launch(void* const* d_in, const int* in_sizes, int n_in,
                              void* d_out, int out_size) {
    const float* x     = (const float*)d_in[0];
    const int*   ei    = (const int*)d_in[1];
    const int*   batch = (const int*)d_in[2];
    const float* W1 = (const float*)d_in[3];
    const float* b1 = (const float*)d_in[4];
    const float* W2 = (const float*)d_in[5];
    const float* b2 = (const float*)d_in[6];
    const float* W3 = (const float*)d_in[7];
    const float* b3 = (const float*)d_in[8];
    const float* W4 = (const float*)d_in[9];
    const float* b4 = (const float*)d_in[10];
    const float* Wl = (const float*)d_in[11];
    const float* bl = (const float*)d_in[12];
    float* out = (float*)d_out;

    __half *a0, *a1, *w1, *w2, *w3, *w4;
    float* out2;
    cudaGetSymbolAddress((void**)&a0, g_a0);
    cudaGetSymbolAddress((void**)&a1, g_a1);
    cudaGetSymbolAddress((void**)&w1, g_w1);
    cudaGetSymbolAddress((void**)&w2, g_w2);
    cudaGetSymbolAddress((void**)&w3, g_w3);
    cudaGetSymbolAddress((void**)&w4, g_w4);
    cudaGetSymbolAddress((void**)&out2, g_out2);

    cudaFuncSetAttribute(gemm_mma_kernel<1>, cudaFuncAttributeMaxDynamicSharedMemorySize, GEMM_SMEM);
    cudaFuncSetAttribute(gemm_mma_kernel<2>, cudaFuncAttributeMaxDynamicSharedMemorySize, GEMM_SMEM);
    cudaFuncSetAttribute(gemm_mma_kernel<3>, cudaFuncAttributeMaxDynamicSharedMemorySize, GEMM_SMEM);
    cudaFuncSetAttribute(gemm_mma_kernel<4>, cudaFuncAttributeMaxDynamicSharedMemorySize, GEMM_SMEM);

    // 1) prep (convW, zeros, counts) + CSR build + aggregation
    prep0_kernel<<<(PREP_THREADS + 255) / 256, 256>>>(W1, W2, W3, W4, batch);
    hist_kernel<<<(EE + 255) / 256, 256>>>(ei);
    scan1_kernel<<<NBLK, 256>>>();
    scan2_kernel<<<1, 256>>>();
    scatter_kernel<<<(EE + 255) / 256, 256>>>(ei);
    csr_agg_kernel<<<(NN * 32 + 255) / 256, 256>>>(x);

    // 2) MLP: 3 node-level GEMMs (layer 3 fuses ReLU+mean-pool),
    //    then layer 4 on POOLED features (512 rows; pooling commutes with linear)
    dim3 grid(DH / 128, (NN + 127) / 128);
    gemm_mma_kernel<1><<<grid, GT, GEMM_SMEM>>>(a0, w1, b1, a1, nullptr, nullptr, NN, DIN);
    gemm_mma_kernel<2><<<grid, GT, GEMM_SMEM>>>(a1, w2, b2, a0, nullptr, nullptr, NN, DH);
    gemm_mma_kernel<3><<<grid, GT, GEMM_SMEM>>>(a0, w3, b3, nullptr, nullptr, batch, NN, DH);

    pool2half_kernel<<<(GG * DH + 255) / 256, 256>>>(a1);
    dim3 grid4(DH / 128, GG / 128);
    gemm_mma_kernel<4><<<grid4, GT, GEMM_SMEM>>>(a1, w4, b4, nullptr, out2, nullptr, GG, DH);

    // 3) final linear + L2 normalize
    final_out_kernel<<<GG, DOUT>>>(Wl, bl, out);
}